// round 1
// baseline (speedup 1.0000x reference)
#include <cuda_runtime.h>
#include <cuda_bf16.h>

#define EPSF 1e-10f

// Scratch accumulator (no allocations allowed).
__device__ double g_acc;

__global__ void zero_acc_kernel() { g_acc = 0.0; }

__device__ __forceinline__ float elem_term(float p, int y, float lam) {
    // y==0 -> -log(1 - p + eps); else -> -lam * log(p + eps)
    // One MUFU log per element: select argument and scale by predicate.
    bool neg = (y == 0);
    float arg = neg ? (1.0f - p + EPSF) : (p + EPSF);
    float scale = neg ? 1.0f : lam;
    return -scale * __logf(arg);
}

__global__ void __launch_bounds__(256)
sparse_loss_kernel(const float* __restrict__ pred,
                   const int* __restrict__ y,
                   const int* __restrict__ lamda_raw,
                   long long n) {
    // Disambiguate lamda dtype: small non-negative int bit-pattern -> integer,
    // otherwise treat the 32 bits as float. (int 5 and float 5.0f both -> 5.0f)
    int ibits = *lamda_raw;
    float lam = (ibits >= 0 && ibits < 1000000) ? (float)ibits : __int_as_float(ibits);

    long long nvec = n >> 2;   // float4 count
    const float4* __restrict__ p4 = (const float4*)pred;
    const int4*   __restrict__ y4 = (const int4*)y;

    float acc = 0.0f;
    long long tid    = (long long)blockIdx.x * blockDim.x + threadIdx.x;
    long long stride = (long long)gridDim.x * blockDim.x;

    for (long long i = tid; i < nvec; i += stride) {
        float4 p = p4[i];
        int4   t = y4[i];
        acc += elem_term(p.x, t.x, lam);
        acc += elem_term(p.y, t.y, lam);
        acc += elem_term(p.z, t.z, lam);
        acc += elem_term(p.w, t.w, lam);
    }
    // scalar tail (n not divisible by 4)
    for (long long i = (nvec << 2) + tid; i < n; i += stride) {
        acc += elem_term(pred[i], y[i], lam);
    }

    // warp reduce
    #pragma unroll
    for (int off = 16; off > 0; off >>= 1)
        acc += __shfl_down_sync(0xFFFFFFFFu, acc, off);

    __shared__ float wsum[8];
    int lane = threadIdx.x & 31;
    int warp = threadIdx.x >> 5;
    if (lane == 0) wsum[warp] = acc;
    __syncthreads();

    if (warp == 0) {
        float b = (lane < (blockDim.x >> 5)) ? wsum[lane] : 0.0f;
        #pragma unroll
        for (int off = 4; off > 0; off >>= 1)
            b += __shfl_down_sync(0xFFFFFFFFu, b, off);
        if (lane == 0)
            atomicAdd(&g_acc, (double)b);
    }
}

__global__ void finalize_kernel(float* __restrict__ out, long long n) {
    out[0] = (float)(g_acc / (double)n);
}

extern "C" void kernel_launch(void* const* d_in, const int* in_sizes, int n_in,
                              void* d_out, int out_size) {
    const float* pred  = (const float*)d_in[0];
    const int*   y     = (const int*)d_in[1];
    const int*   lamda = (const int*)d_in[2];
    long long n = (long long)in_sizes[0];

    zero_acc_kernel<<<1, 1>>>();

    const int threads = 256;
    int blocks = 148 * 8;  // 8 CTAs per SM on 148-SM GB300 (152 avail)
    long long nvec = n >> 2;
    long long need = (nvec + threads - 1) / threads;
    if ((long long)blocks > need && need > 0) blocks = (int)need;
    if (blocks < 1) blocks = 1;

    sparse_loss_kernel<<<blocks, threads>>>(pred, y, lamda, n);
    finalize_kernel<<<1, 1>>>((float*)d_out, n);
}

// round 2
// speedup vs baseline: 1.0756x; 1.0756x over previous
#include <cuda_runtime.h>
#include <cuda_bf16.h>

#define EPSF 1e-10f

// Persistent scratch (no allocations allowed). Reset by the last block each
// run, so every graph replay starts from a clean state.
__device__ double g_acc = 0.0;
__device__ unsigned int g_done = 0;

__device__ __forceinline__ float elem_term(float p, int y, float lam) {
    // y==0 -> -log(1 - p + eps); else -> -lam * log(p + eps)
    bool neg = (y == 0);
    float arg   = neg ? (1.0f - p + EPSF) : (p + EPSF);
    float scale = neg ? 1.0f : lam;
    return -scale * __logf(arg);
}

__global__ void __launch_bounds__(256)
sparse_loss_fused(const float* __restrict__ pred,
                  const int* __restrict__ y,
                  const int* __restrict__ lamda_raw,
                  float* __restrict__ out,
                  long long n) {
    // Disambiguate lamda dtype: small non-negative int bit-pattern -> integer,
    // otherwise reinterpret bits as float. (int 5 and float 5.0f both -> 5.0f)
    int ibits = *lamda_raw;
    float lam = (ibits >= 0 && ibits < 1000000) ? (float)ibits : __int_as_float(ibits);

    long long nvec = n >> 2;
    const float4* __restrict__ p4 = (const float4*)pred;
    const int4*   __restrict__ y4 = (const int4*)y;

    long long tid    = (long long)blockIdx.x * blockDim.x + threadIdx.x;
    long long stride = (long long)gridDim.x * blockDim.x;

    float acc = 0.0f;

    // 4-way batched grid-stride: 8 x 16B loads in flight per iteration (MLP).
    // Streaming loads (.cs) — each byte is touched exactly once.
    long long i = tid;
    for (; i + 3 * stride < nvec; i += 4 * stride) {
        float4 p0 = __ldcs(p4 + i);
        float4 p1 = __ldcs(p4 + i + stride);
        float4 p2 = __ldcs(p4 + i + 2 * stride);
        float4 p3 = __ldcs(p4 + i + 3 * stride);
        int4   t0 = __ldcs(y4 + i);
        int4   t1 = __ldcs(y4 + i + stride);
        int4   t2 = __ldcs(y4 + i + 2 * stride);
        int4   t3 = __ldcs(y4 + i + 3 * stride);
        acc += elem_term(p0.x, t0.x, lam) + elem_term(p0.y, t0.y, lam)
             + elem_term(p0.z, t0.z, lam) + elem_term(p0.w, t0.w, lam);
        acc += elem_term(p1.x, t1.x, lam) + elem_term(p1.y, t1.y, lam)
             + elem_term(p1.z, t1.z, lam) + elem_term(p1.w, t1.w, lam);
        acc += elem_term(p2.x, t2.x, lam) + elem_term(p2.y, t2.y, lam)
             + elem_term(p2.z, t2.z, lam) + elem_term(p2.w, t2.w, lam);
        acc += elem_term(p3.x, t3.x, lam) + elem_term(p3.y, t3.y, lam)
             + elem_term(p3.z, t3.z, lam) + elem_term(p3.w, t3.w, lam);
    }
    for (; i < nvec; i += stride) {
        float4 p = __ldcs(p4 + i);
        int4   t = __ldcs(y4 + i);
        acc += elem_term(p.x, t.x, lam) + elem_term(p.y, t.y, lam)
             + elem_term(p.z, t.z, lam) + elem_term(p.w, t.w, lam);
    }
    // scalar tail (n not divisible by 4)
    for (long long j = (nvec << 2) + tid; j < n; j += stride) {
        acc += elem_term(pred[j], y[j], lam);
    }

    // warp reduce
    #pragma unroll
    for (int off = 16; off > 0; off >>= 1)
        acc += __shfl_down_sync(0xFFFFFFFFu, acc, off);

    __shared__ float wsum[8];
    int lane = threadIdx.x & 31;
    int warp = threadIdx.x >> 5;
    if (lane == 0) wsum[warp] = acc;
    __syncthreads();

    __shared__ bool s_last;
    if (warp == 0) {
        float b = (lane < (blockDim.x >> 5)) ? wsum[lane] : 0.0f;
        #pragma unroll
        for (int off = 4; off > 0; off >>= 1)
            b += __shfl_down_sync(0xFFFFFFFFu, b, off);
        if (lane == 0) {
            atomicAdd(&g_acc, (double)b);
            __threadfence();
            unsigned prev = atomicAdd(&g_done, 1u);
            s_last = (prev == gridDim.x - 1);
        }
    }
    __syncthreads();

    // Last block to finish: publish result and reset state for next replay.
    if (s_last && threadIdx.x == 0) {
        double total = atomicAdd(&g_acc, 0.0);  // fenced read
        out[0] = (float)(total / (double)n);
        g_acc = 0.0;
        __threadfence();
        g_done = 0;
    }
}

extern "C" void kernel_launch(void* const* d_in, const int* in_sizes, int n_in,
                              void* d_out, int out_size) {
    const float* pred  = (const float*)d_in[0];
    const int*   y     = (const int*)d_in[1];
    const int*   lamda = (const int*)d_in[2];
    long long n = (long long)in_sizes[0];

    const int threads = 256;
    int blocks = 148 * 8;  // full occupancy: 2048 threads/SM on 148+ SMs
    long long nvec = (n >> 2) > 0 ? (n >> 2) : 1;
    long long need = (nvec + threads - 1) / threads;
    if ((long long)blocks > need && need > 0) blocks = (int)need;
    if (blocks < 1) blocks = 1;

    sparse_loss_fused<<<blocks, threads>>>(pred, y, lamda, (float*)d_out, n);
}

// round 3
// speedup vs baseline: 1.0846x; 1.0084x over previous
#include <cuda_runtime.h>
#include <cuda_bf16.h>

#define EPSF 1e-10f

// Persistent scratch (no allocations allowed). Reset by the last block each
// run, so every graph replay starts from a clean state.
__device__ double g_acc = 0.0;
__device__ unsigned int g_done = 0;

__device__ __forceinline__ float elem_term(float p, int y, float lam) {
    // y==0 -> -log(1 - p + eps); else -> -lam * log(p + eps)
    bool neg = (y == 0);
    float arg   = neg ? (1.0f - p + EPSF) : (p + EPSF);
    float scale = neg ? 1.0f : lam;
    return -scale * __logf(arg);
}

__global__ void __launch_bounds__(256, 8)
sparse_loss_fused(const float* __restrict__ pred,
                  const int* __restrict__ y,
                  const int* __restrict__ lamda_raw,
                  float* __restrict__ out,
                  int n) {
    // Disambiguate lamda dtype: small non-negative int bit-pattern -> integer,
    // otherwise reinterpret bits as float. (int 5 and float 5.0f both -> 5.0f)
    int ibits = *lamda_raw;
    float lam = (ibits >= 0 && ibits < 1000000) ? (float)ibits : __int_as_float(ibits);

    int nvec = n >> 2;  // float4 count
    const float4* __restrict__ p4 = (const float4*)pred;
    const int4*   __restrict__ y4 = (const int4*)y;

    int tid    = blockIdx.x * blockDim.x + threadIdx.x;
    int stride = gridDim.x * blockDim.x;

    float acc = 0.0f;

    // 2-way batched grid-stride: 4 x 16B loads in flight per iteration.
    // 32-bit indexing keeps register count <= 32 so 8 CTAs/SM fit (2048 thr).
    int i = tid;
    for (; i + stride < nvec; i += 2 * stride) {
        float4 p0 = __ldcs(p4 + i);
        float4 p1 = __ldcs(p4 + i + stride);
        int4   t0 = __ldcs(y4 + i);
        int4   t1 = __ldcs(y4 + i + stride);
        acc += elem_term(p0.x, t0.x, lam) + elem_term(p0.y, t0.y, lam)
             + elem_term(p0.z, t0.z, lam) + elem_term(p0.w, t0.w, lam);
        acc += elem_term(p1.x, t1.x, lam) + elem_term(p1.y, t1.y, lam)
             + elem_term(p1.z, t1.z, lam) + elem_term(p1.w, t1.w, lam);
    }
    if (i < nvec) {
        float4 p = __ldcs(p4 + i);
        int4   t = __ldcs(y4 + i);
        acc += elem_term(p.x, t.x, lam) + elem_term(p.y, t.y, lam)
             + elem_term(p.z, t.z, lam) + elem_term(p.w, t.w, lam);
    }
    // scalar tail (n not divisible by 4)
    for (int j = (nvec << 2) + tid; j < n; j += stride) {
        acc += elem_term(pred[j], y[j], lam);
    }

    // warp reduce
    #pragma unroll
    for (int off = 16; off > 0; off >>= 1)
        acc += __shfl_down_sync(0xFFFFFFFFu, acc, off);

    __shared__ float wsum[8];
    int lane = threadIdx.x & 31;
    int warp = threadIdx.x >> 5;
    if (lane == 0) wsum[warp] = acc;
    __syncthreads();

    __shared__ bool s_last;
    if (warp == 0) {
        float b = (lane < (blockDim.x >> 5)) ? wsum[lane] : 0.0f;
        #pragma unroll
        for (int off = 4; off > 0; off >>= 1)
            b += __shfl_down_sync(0xFFFFFFFFu, b, off);
        if (lane == 0) {
            atomicAdd(&g_acc, (double)b);
            __threadfence();
            unsigned prev = atomicAdd(&g_done, 1u);
            s_last = (prev == gridDim.x - 1);
        }
    }
    __syncthreads();

    // Last block to finish: publish result and reset state for next replay.
    if (s_last && threadIdx.x == 0) {
        double total = atomicAdd(&g_acc, 0.0);  // fenced read
        out[0] = (float)(total / (double)n);
        g_acc = 0.0;
        __threadfence();
        g_done = 0;
    }
}

extern "C" void kernel_launch(void* const* d_in, const int* in_sizes, int n_in,
                              void* d_out, int out_size) {
    const float* pred  = (const float*)d_in[0];
    const int*   y     = (const int*)d_in[1];
    const int*   lamda = (const int*)d_in[2];
    int n = in_sizes[0];

    const int threads = 256;
    int blocks = 148 * 8;  // one full wave at 8 CTAs/SM
    int nvec = (n >> 2) > 0 ? (n >> 2) : 1;
    int need = (nvec + threads - 1) / threads;
    if (blocks > need && need > 0) blocks = need;
    if (blocks < 1) blocks = 1;

    sparse_loss_fused<<<blocks, threads>>>(pred, y, lamda, (float*)d_out, n);
}